// round 1
// baseline (speedup 1.0000x reference)
#include <cuda_runtime.h>
#include <cstdint>

// Problem dims (fixed by the dataset)
#define BB 256
#define TT 256
#define DD 128
#define HH 256
#define NROWS (BB*TT)          // 65536

// Scratch: h1/spikes [B,T,H] and h2 [B,T,D]
__device__ __align__(16) float g_h1[(size_t)NROWS * HH];   // 67 MB
__device__ __align__(16) float g_h2[(size_t)NROWS * DD];   // 33.5 MB

// ---------------------------------------------------------------------------
// GEMM1 + bias + LayerNorm(H):  h1[row][h] = LN( dot(x[row,:], W1[h,:]) + b1 )
// Block: 32 rows, full H=256. W1 (256x128) staged in smem, padded rows (132).
// Thread tile: 4 h  x 8 rows.
// ---------------------------------------------------------------------------
#define G1_SMEM_FLOATS (256*132 + 32*132 + 32*260)
__global__ __launch_bounds__(256, 1)
void gemm1_ln_kernel(const float* __restrict__ x,
                     const float* __restrict__ W1,
                     const float* __restrict__ b1,
                     const float* __restrict__ g1,
                     const float* __restrict__ be1)
{
    extern __shared__ float sm[];
    float* ws = sm;                 // [256][132]
    float* xs = ws + 256*132;       // [32][132]
    float* hs = xs + 32*132;        // [32][260]

    const int tid = threadIdx.x;
    const int rowBase = blockIdx.x * 32;

    // Stage W1 [h][k] -> ws[h*132 + k] (float4, coalesced)
    const float4* W4 = (const float4*)W1;        // 8192 float4
    #pragma unroll
    for (int i = 0; i < 32; i++) {
        int idx = tid + i*256;
        int h = idx >> 5, k4 = (idx & 31) << 2;
        *(float4*)(ws + h*132 + k4) = W4[idx];
    }
    // Stage x rows -> xs[r*132 + k]
    const float4* X4 = (const float4*)(x + (size_t)rowBase * DD);  // 1024 float4
    #pragma unroll
    for (int i = 0; i < 4; i++) {
        int idx = tid + i*256;
        int r = idx >> 5, k4 = (idx & 31) << 2;
        *(float4*)(xs + r*132 + k4) = X4[idx];
    }
    __syncthreads();

    const int hgrp = tid & 63;      // h = hgrp + 64*j
    const int rgrp = tid >> 6;      // rows rgrp*8 .. +7

    float acc[4][8];
    #pragma unroll
    for (int j = 0; j < 4; j++)
        #pragma unroll
        for (int r = 0; r < 8; r++) acc[j][r] = 0.f;

    const float* wp[4];
    const float* xp[8];
    #pragma unroll
    for (int j = 0; j < 4; j++) wp[j] = ws + (hgrp + 64*j)*132;
    #pragma unroll
    for (int r = 0; r < 8; r++) xp[r] = xs + (rgrp*8 + r)*132;

    #pragma unroll 4
    for (int kc = 0; kc < 128; kc += 4) {
        float4 wv[4], xv[8];
        #pragma unroll
        for (int j = 0; j < 4; j++) wv[j] = *(const float4*)(wp[j] + kc);
        #pragma unroll
        for (int r = 0; r < 8; r++) xv[r] = *(const float4*)(xp[r] + kc);
        #pragma unroll
        for (int j = 0; j < 4; j++)
            #pragma unroll
            for (int r = 0; r < 8; r++) {
                acc[j][r] += wv[j].x * xv[r].x;
                acc[j][r] += wv[j].y * xv[r].y;
                acc[j][r] += wv[j].z * xv[r].z;
                acc[j][r] += wv[j].w * xv[r].w;
            }
    }

    // bias + stage for LN
    #pragma unroll
    for (int j = 0; j < 4; j++) {
        int h = hgrp + 64*j;
        float bb = b1[h];
        #pragma unroll
        for (int r = 0; r < 8; r++)
            hs[(rgrp*8 + r)*260 + h] = acc[j][r] + bb;
    }
    __syncthreads();

    // LayerNorm over H=256 per row: 8 warps x 4 rows
    const int lane = tid & 31, wrp = tid >> 5;
    #pragma unroll
    for (int rr = 0; rr < 4; rr++) {
        int row = wrp*4 + rr;
        float vals[8], sum = 0.f, sq = 0.f;
        #pragma unroll
        for (int i = 0; i < 8; i++) {
            float v = hs[row*260 + lane + 32*i];
            vals[i] = v; sum += v; sq += v*v;
        }
        #pragma unroll
        for (int o = 16; o; o >>= 1) {
            sum += __shfl_xor_sync(0xffffffffu, sum, o);
            sq  += __shfl_xor_sync(0xffffffffu, sq,  o);
        }
        float mean = sum * (1.f/256.f);
        float var  = fmaxf(sq * (1.f/256.f) - mean*mean, 0.f) + 1e-5f;
        float inv  = rsqrtf(var);
        inv = inv * (1.5f - 0.5f * var * inv * inv);   // Newton -> fp32-exact rsqrt
        float* op = g_h1 + (size_t)(rowBase + row) * HH;
        #pragma unroll
        for (int i = 0; i < 8; i++) {
            int h = lane + 32*i;
            op[h] = (vals[i] - mean) * inv * g1[h] + be1[h];
        }
    }
}

// ---------------------------------------------------------------------------
// LIF scan 1 (in-place on g_h1): per (b, h4-lane), scan T. TAU=2, V_TH=1,
// hard reset to 0.  h = v + (x - v)*0.5; s = (h>=1); v = s?0:h.
// ---------------------------------------------------------------------------
__global__ __launch_bounds__(256)
void lif1_kernel()
{
    int tid = blockIdx.x * 256 + threadIdx.x;     // 16384 lanes
    int b = tid >> 6, h4 = tid & 63;              // HH/4 = 64 float4 per (b,t)
    float4* p = reinterpret_cast<float4*>(g_h1) + (size_t)b * (TT * 64) + h4;
    float4 v = make_float4(0.f, 0.f, 0.f, 0.f);
    #pragma unroll 4
    for (int t = 0; t < TT; t++) {
        float4 c = p[(size_t)t * 64];
        float4 s;
        float hm;
        hm = v.x + (c.x - v.x)*0.5f; s.x = (hm >= 1.f) ? 1.f : 0.f; v.x = (hm >= 1.f) ? 0.f : hm;
        hm = v.y + (c.y - v.y)*0.5f; s.y = (hm >= 1.f) ? 1.f : 0.f; v.y = (hm >= 1.f) ? 0.f : hm;
        hm = v.z + (c.z - v.z)*0.5f; s.z = (hm >= 1.f) ? 1.f : 0.f; v.z = (hm >= 1.f) ? 0.f : hm;
        hm = v.w + (c.w - v.w)*0.5f; s.w = (hm >= 1.f) ? 1.f : 0.f; v.w = (hm >= 1.f) ? 0.f : hm;
        p[(size_t)t * 64] = s;
    }
}

// ---------------------------------------------------------------------------
// GEMM2 + bias + LayerNorm(D): h2[row][d] = LN( dot(s[row,:], W2[d,:]) + b2 )
// Block: 32 rows, full D=128. W2 (128x256) staged in smem (row pad 260).
// Thread tile: 4 d x 4 rows.
// ---------------------------------------------------------------------------
#define G2_SMEM_FLOATS (128*260 + 32*260 + 32*132)
__global__ __launch_bounds__(256, 1)
void gemm2_ln_kernel(const float* __restrict__ W2,
                     const float* __restrict__ b2,
                     const float* __restrict__ g2,
                     const float* __restrict__ be2)
{
    extern __shared__ float sm[];
    float* ws = sm;                 // [128][260]
    float* ss = ws + 128*260;       // [32][260]
    float* os = ss + 32*260;        // [32][132]

    const int tid = threadIdx.x;
    const int rowBase = blockIdx.x * 32;

    // Stage W2 [d][h] -> ws[d*260 + h]
    const float4* W4 = (const float4*)W2;        // 8192 float4
    #pragma unroll
    for (int i = 0; i < 32; i++) {
        int idx = tid + i*256;
        int d = idx >> 6, h4 = (idx & 63) << 2;
        *(float4*)(ws + d*260 + h4) = W4[idx];
    }
    // Stage spike rows from g_h1
    const float4* S4 = (const float4*)(g_h1 + (size_t)rowBase * HH);  // 2048 float4
    #pragma unroll
    for (int i = 0; i < 8; i++) {
        int idx = tid + i*256;
        int r = idx >> 6, h4 = (idx & 63) << 2;
        *(float4*)(ss + r*260 + h4) = S4[idx];
    }
    __syncthreads();

    const int dgrp = tid & 31;      // d = dgrp + 32*j
    const int rgrp = tid >> 5;      // rows rgrp*4 .. +3

    float acc[4][4];
    #pragma unroll
    for (int j = 0; j < 4; j++)
        #pragma unroll
        for (int r = 0; r < 4; r++) acc[j][r] = 0.f;

    const float* wp[4];
    const float* sp[4];
    #pragma unroll
    for (int j = 0; j < 4; j++) wp[j] = ws + (dgrp + 32*j)*260;
    #pragma unroll
    for (int r = 0; r < 4; r++) sp[r] = ss + (rgrp*4 + r)*260;

    #pragma unroll 4
    for (int hc = 0; hc < 256; hc += 4) {
        float4 wv[4], sv[4];
        #pragma unroll
        for (int j = 0; j < 4; j++) wv[j] = *(const float4*)(wp[j] + hc);
        #pragma unroll
        for (int r = 0; r < 4; r++) sv[r] = *(const float4*)(sp[r] + hc);
        #pragma unroll
        for (int j = 0; j < 4; j++)
            #pragma unroll
            for (int r = 0; r < 4; r++) {
                acc[j][r] += wv[j].x * sv[r].x;
                acc[j][r] += wv[j].y * sv[r].y;
                acc[j][r] += wv[j].z * sv[r].z;
                acc[j][r] += wv[j].w * sv[r].w;
            }
    }

    #pragma unroll
    for (int j = 0; j < 4; j++) {
        int d = dgrp + 32*j;
        float bb = b2[d];
        #pragma unroll
        for (int r = 0; r < 4; r++)
            os[(rgrp*4 + r)*132 + d] = acc[j][r] + bb;
    }
    __syncthreads();

    // LayerNorm over D=128 per row: 8 warps x 4 rows
    const int lane = tid & 31, wrp = tid >> 5;
    #pragma unroll
    for (int rr = 0; rr < 4; rr++) {
        int row = wrp*4 + rr;
        float vals[4], sum = 0.f, sq = 0.f;
        #pragma unroll
        for (int i = 0; i < 4; i++) {
            float v = os[row*132 + lane + 32*i];
            vals[i] = v; sum += v; sq += v*v;
        }
        #pragma unroll
        for (int o = 16; o; o >>= 1) {
            sum += __shfl_xor_sync(0xffffffffu, sum, o);
            sq  += __shfl_xor_sync(0xffffffffu, sq,  o);
        }
        float mean = sum * (1.f/128.f);
        float var  = fmaxf(sq * (1.f/128.f) - mean*mean, 0.f) + 1e-5f;
        float inv  = rsqrtf(var);
        inv = inv * (1.5f - 0.5f * var * inv * inv);
        float* op = g_h2 + (size_t)(rowBase + row) * DD;
        #pragma unroll
        for (int i = 0; i < 4; i++) {
            int d = lane + 32*i;
            op[d] = (vals[i] - mean) * inv * g2[d] + be2[d];
        }
    }
}

// ---------------------------------------------------------------------------
// LIF scan 2 + residual: out[b,t,d] = x[b,t,d] + spike(h2 scan)
// ---------------------------------------------------------------------------
__global__ __launch_bounds__(256)
void lif2_kernel(const float* __restrict__ x, float* __restrict__ out)
{
    int tid = blockIdx.x * 256 + threadIdx.x;     // 8192 lanes
    int b = tid >> 5, d4 = tid & 31;              // DD/4 = 32 float4 per (b,t)
    size_t base = (size_t)b * (TT * 32) + d4;
    const float4* hp = reinterpret_cast<const float4*>(g_h2) + base;
    const float4* xp = reinterpret_cast<const float4*>(x) + base;
    float4* op = reinterpret_cast<float4*>(out) + base;
    float4 v = make_float4(0.f, 0.f, 0.f, 0.f);
    #pragma unroll 4
    for (int t = 0; t < TT; t++) {
        float4 c  = hp[(size_t)t * 32];
        float4 xv = xp[(size_t)t * 32];
        float4 o;
        float hm;
        hm = v.x + (c.x - v.x)*0.5f; o.x = xv.x + ((hm >= 1.f) ? 1.f : 0.f); v.x = (hm >= 1.f) ? 0.f : hm;
        hm = v.y + (c.y - v.y)*0.5f; o.y = xv.y + ((hm >= 1.f) ? 1.f : 0.f); v.y = (hm >= 1.f) ? 0.f : hm;
        hm = v.z + (c.z - v.z)*0.5f; o.z = xv.z + ((hm >= 1.f) ? 1.f : 0.f); v.z = (hm >= 1.f) ? 0.f : hm;
        hm = v.w + (c.w - v.w)*0.5f; o.w = xv.w + ((hm >= 1.f) ? 1.f : 0.f); v.w = (hm >= 1.f) ? 0.f : hm;
        op[(size_t)t * 32] = o;
    }
}

// ---------------------------------------------------------------------------
extern "C" void kernel_launch(void* const* d_in, const int* in_sizes, int n_in,
                              void* d_out, int out_size)
{
    const float* x   = (const float*)d_in[0];
    const float* W1  = (const float*)d_in[1];
    const float* b1  = (const float*)d_in[2];
    const float* g1  = (const float*)d_in[3];
    const float* be1 = (const float*)d_in[4];
    const float* W2  = (const float*)d_in[5];
    const float* b2  = (const float*)d_in[6];
    const float* g2  = (const float*)d_in[7];
    const float* be2 = (const float*)d_in[8];
    float* out = (float*)d_out;

    (void)in_sizes; (void)n_in; (void)out_size;

    const size_t g1_smem = G1_SMEM_FLOATS * sizeof(float);   // 185344 B
    const size_t g2_smem = G2_SMEM_FLOATS * sizeof(float);   // 183296 B
    cudaFuncSetAttribute(gemm1_ln_kernel,
                         cudaFuncAttributeMaxDynamicSharedMemorySize, (int)g1_smem);
    cudaFuncSetAttribute(gemm2_ln_kernel,
                         cudaFuncAttributeMaxDynamicSharedMemorySize, (int)g2_smem);

    gemm1_ln_kernel<<<NROWS/32, 256, g1_smem>>>(x, W1, b1, g1, be1);
    lif1_kernel<<<(BB*HH/4)/256, 256>>>();
    gemm2_ln_kernel<<<NROWS/32, 256, g2_smem>>>(W2, b2, g2, be2);
    lif2_kernel<<<(BB*DD/4)/256, 256>>>(x, out);
}

// round 2
// speedup vs baseline: 1.3080x; 1.3080x over previous
#include <cuda_runtime.h>
#include <cstdint>

// Problem dims (fixed by the dataset)
#define BB 256
#define TT 256
#define DD 128
#define HH 256
#define NROWS (BB*TT)          // 65536

// Scratch: h1/spikes [B,T,H] and h2 [B,T,D]
__device__ __align__(16) float g_h1[(size_t)NROWS * HH];   // 67 MB
__device__ __align__(16) float g_h2[(size_t)NROWS * DD];   // 33.5 MB

// ---------------------------------------------------------------------------
// packed fp32x2 helpers (sm_10x FFMA2 — PTX-only, ptxas never auto-emits)
// ---------------------------------------------------------------------------
__device__ __forceinline__ unsigned long long pack2(float lo, float hi) {
    unsigned long long p;
    asm("mov.b64 %0, {%1, %2};" : "=l"(p) : "f"(lo), "f"(hi));
    return p;
}
__device__ __forceinline__ void unpack2(unsigned long long p, float& lo, float& hi) {
    asm("mov.b64 {%0, %1}, %2;" : "=f"(lo), "=f"(hi) : "l"(p));
}
__device__ __forceinline__ void fma2(unsigned long long& acc,
                                     unsigned long long a, unsigned long long b) {
    asm("fma.rn.f32x2 %0, %1, %2, %0;" : "+l"(acc) : "l"(a), "l"(b));
}

// ---------------------------------------------------------------------------
// GEMM1 + bias + LayerNorm(H):  g_h1[row][h] = LN( dot(x[row,:], W1[h,:]) + b1 )
// Block: 64 rows, full H=256. W1 staged k-major [128][260] for f32x2 pairs.
// Warp owns 8 rows; lane owns h = {2l,2l+1} + 64j (j<4)  -> acc[4][8] f32x2.
// LN fully warp-local (no smem staging of h).
// ---------------------------------------------------------------------------
#define G1_SMEM_FLOATS (128*260 + 64*132)
__global__ __launch_bounds__(256, 1)
void gemm1_ln_kernel(const float* __restrict__ x,
                     const float* __restrict__ W1,
                     const float* __restrict__ b1,
                     const float* __restrict__ g1,
                     const float* __restrict__ be1)
{
    extern __shared__ float sm[];
    float* wst = sm;                 // [k=128][h pad 260]
    float* xs  = sm + 128*260;       // [r=64][k pad 132]

    const int tid = threadIdx.x;
    const int rowBase = blockIdx.x * 64;

    // Stage W1 transposed: thread tid owns h=tid, streams its gmem row.
    {
        const float4* W4 = (const float4*)W1;       // [h][k4] 256x32
        const int h = tid;
        #pragma unroll
        for (int i = 0; i < 32; i++) {
            float4 v = W4[h*32 + i];
            int k = i*4;
            wst[(k+0)*260 + h] = v.x;
            wst[(k+1)*260 + h] = v.y;
            wst[(k+2)*260 + h] = v.z;
            wst[(k+3)*260 + h] = v.w;
        }
    }
    // Stage x rows (coalesced float4)
    {
        const float4* X4 = (const float4*)(x + (size_t)rowBase * DD);  // 2048 float4
        #pragma unroll
        for (int i = 0; i < 8; i++) {
            int idx = tid + i*256;
            int r = idx >> 5, k4 = (idx & 31) << 2;
            *(float4*)(xs + r*132 + k4) = X4[idx];
        }
    }
    __syncthreads();

    const int lane = tid & 31;
    const int wrp  = tid >> 5;
    const int rowOff = wrp * 8;

    unsigned long long acc[4][8];
    #pragma unroll
    for (int j = 0; j < 4; j++) {
        float2 bb = *(const float2*)(b1 + 2*lane + 64*j);
        unsigned long long bp = pack2(bb.x, bb.y);
        #pragma unroll
        for (int r = 0; r < 8; r++) acc[j][r] = bp;
    }

    #pragma unroll 4
    for (int k = 0; k < 128; k++) {
        unsigned long long wv[4];
        #pragma unroll
        for (int j = 0; j < 4; j++)
            wv[j] = *(const unsigned long long*)(wst + k*260 + 2*lane + 64*j);
        #pragma unroll
        for (int r = 0; r < 8; r++) {
            float xsc = xs[(rowOff + r)*132 + k];
            unsigned long long xp = pack2(xsc, xsc);
            #pragma unroll
            for (int j = 0; j < 4; j++) fma2(acc[j][r], wv[j], xp);
        }
    }

    // Warp-local LayerNorm per row (256 h spread over 32 lanes x 8 values)
    #pragma unroll
    for (int r = 0; r < 8; r++) {
        float v[8];
        #pragma unroll
        for (int j = 0; j < 4; j++) unpack2(acc[j][r], v[2*j], v[2*j+1]);
        float sum = 0.f, sq = 0.f;
        #pragma unroll
        for (int i = 0; i < 8; i++) { sum += v[i]; sq += v[i]*v[i]; }
        #pragma unroll
        for (int o = 16; o; o >>= 1) {
            sum += __shfl_xor_sync(0xffffffffu, sum, o);
            sq  += __shfl_xor_sync(0xffffffffu, sq,  o);
        }
        float mean = sum * (1.f/256.f);
        float var  = fmaxf(sq * (1.f/256.f) - mean*mean, 0.f) + 1e-5f;
        float inv  = rsqrtf(var);
        inv = inv * (1.5f - 0.5f * var * inv * inv);   // Newton -> fp32-exact rsqrt
        float* op = g_h1 + (size_t)(rowBase + rowOff + r) * HH;
        #pragma unroll
        for (int j = 0; j < 4; j++) {
            int h = 2*lane + 64*j;
            float2 gg = *(const float2*)(g1 + h);
            float2 bb = *(const float2*)(be1 + h);
            float2 o;
            o.x = (v[2*j]   - mean) * inv * gg.x + bb.x;
            o.y = (v[2*j+1] - mean) * inv * gg.y + bb.y;
            *(float2*)(op + h) = o;
        }
    }
}

// ---------------------------------------------------------------------------
// LIF scan 1 (in-place on g_h1): scalar lanes, one per (b,h). 65536 threads.
// h = v + (x - v)*0.5; s = (h>=1); v = s?0:h (hard reset).
// ---------------------------------------------------------------------------
__global__ __launch_bounds__(256)
void lif1_kernel()
{
    int g = blockIdx.x * 256 + threadIdx.x;    // 65536 lanes
    int b = g >> 8, h = g & 255;
    float* p = g_h1 + (size_t)b * (TT * HH) + h;
    float v = 0.f;
    #pragma unroll 8
    for (int t = 0; t < TT; t++) {
        float c = p[(size_t)t * HH];
        float hm = v + (c - v) * 0.5f;
        p[(size_t)t * HH] = (hm >= 1.f) ? 1.f : 0.f;
        v = (hm >= 1.f) ? 0.f : hm;
    }
}

// ---------------------------------------------------------------------------
// GEMM2 + bias + LayerNorm(D): g_h2[row][d] = LN( dot(s[row,:], W2[d,:]) + b2 )
// Block: 64 rows, full D=128. W2 staged k-major [256][132].
// Warp owns 8 rows; lane owns d = {2l,2l+1} + 64j (j<2) -> acc[2][8] f32x2.
// ---------------------------------------------------------------------------
#define G2_SMEM_FLOATS (256*132 + 64*260)
__global__ __launch_bounds__(256, 1)
void gemm2_ln_kernel(const float* __restrict__ W2,
                     const float* __restrict__ b2,
                     const float* __restrict__ g2,
                     const float* __restrict__ be2)
{
    extern __shared__ float sm[];
    float* wst = sm;                 // [h=256][d pad 132]
    float* ss  = sm + 256*132;       // [r=64][h pad 260]

    const int tid = threadIdx.x;
    const int rowBase = blockIdx.x * 64;

    // Stage W2 transposed: W2 is [d=128][h=256] row-major.
    // Thread pair (tid, tid+128) splits the h range of d = tid & 127.
    {
        const float4* W4 = (const float4*)W2;       // [d][h4] 128x64
        const int d = tid & 127;
        const int hbase4 = (tid >> 7) * 32;          // 0 or 32 (float4 units)
        #pragma unroll
        for (int i = 0; i < 32; i++) {
            float4 v = W4[d*64 + hbase4 + i];
            int h = (hbase4 + i) * 4;
            wst[(h+0)*132 + d] = v.x;
            wst[(h+1)*132 + d] = v.y;
            wst[(h+2)*132 + d] = v.z;
            wst[(h+3)*132 + d] = v.w;
        }
    }
    // Stage spike rows (coalesced float4)
    {
        const float4* S4 = (const float4*)(g_h1 + (size_t)rowBase * HH);  // 4096 float4
        #pragma unroll
        for (int i = 0; i < 16; i++) {
            int idx = tid + i*256;
            int r = idx >> 6, h4 = (idx & 63) << 2;
            *(float4*)(ss + r*260 + h4) = S4[idx];
        }
    }
    __syncthreads();

    const int lane = tid & 31;
    const int wrp  = tid >> 5;
    const int rowOff = wrp * 8;

    unsigned long long acc[2][8];
    #pragma unroll
    for (int j = 0; j < 2; j++) {
        float2 bb = *(const float2*)(b2 + 2*lane + 64*j);
        unsigned long long bp = pack2(bb.x, bb.y);
        #pragma unroll
        for (int r = 0; r < 8; r++) acc[j][r] = bp;
    }

    #pragma unroll 4
    for (int k = 0; k < 256; k++) {
        unsigned long long wv[2];
        #pragma unroll
        for (int j = 0; j < 2; j++)
            wv[j] = *(const unsigned long long*)(wst + k*132 + 2*lane + 64*j);
        #pragma unroll
        for (int r = 0; r < 8; r++) {
            float xsc = ss[(rowOff + r)*260 + k];
            unsigned long long xp = pack2(xsc, xsc);
            #pragma unroll
            for (int j = 0; j < 2; j++) fma2(acc[j][r], wv[j], xp);
        }
    }

    // Warp-local LayerNorm per row (128 d over 32 lanes x 4 values)
    #pragma unroll
    for (int r = 0; r < 8; r++) {
        float v[4];
        #pragma unroll
        for (int j = 0; j < 2; j++) unpack2(acc[j][r], v[2*j], v[2*j+1]);
        float sum = 0.f, sq = 0.f;
        #pragma unroll
        for (int i = 0; i < 4; i++) { sum += v[i]; sq += v[i]*v[i]; }
        #pragma unroll
        for (int o = 16; o; o >>= 1) {
            sum += __shfl_xor_sync(0xffffffffu, sum, o);
            sq  += __shfl_xor_sync(0xffffffffu, sq,  o);
        }
        float mean = sum * (1.f/128.f);
        float var  = fmaxf(sq * (1.f/128.f) - mean*mean, 0.f) + 1e-5f;
        float inv  = rsqrtf(var);
        inv = inv * (1.5f - 0.5f * var * inv * inv);
        float* op = g_h2 + (size_t)(rowBase + rowOff + r) * DD;
        #pragma unroll
        for (int j = 0; j < 2; j++) {
            int d = 2*lane + 64*j;
            float2 gg = *(const float2*)(g2 + d);
            float2 bb = *(const float2*)(be2 + d);
            float2 o;
            o.x = (v[2*j]   - mean) * inv * gg.x + bb.x;
            o.y = (v[2*j+1] - mean) * inv * gg.y + bb.y;
            *(float2*)(op + d) = o;
        }
    }
}

// ---------------------------------------------------------------------------
// LIF scan 2 + residual: scalar lanes, one per (b,d). 32768 threads.
// out[b,t,d] = x[b,t,d] + spike(h2 scan)
// ---------------------------------------------------------------------------
__global__ __launch_bounds__(256)
void lif2_kernel(const float* __restrict__ x, float* __restrict__ out)
{
    int g = blockIdx.x * 256 + threadIdx.x;    // 32768 lanes
    int b = g >> 7, d = g & 127;
    size_t base = (size_t)b * (TT * DD) + d;
    const float* hp = g_h2 + base;
    const float* xp = x + base;
    float* op = out + base;
    float v = 0.f;
    #pragma unroll 8
    for (int t = 0; t < TT; t++) {
        float c  = hp[(size_t)t * DD];
        float xv = xp[(size_t)t * DD];
        float hm = v + (c - v) * 0.5f;
        op[(size_t)t * DD] = xv + ((hm >= 1.f) ? 1.f : 0.f);
        v = (hm >= 1.f) ? 0.f : hm;
    }
}

// ---------------------------------------------------------------------------
extern "C" void kernel_launch(void* const* d_in, const int* in_sizes, int n_in,
                              void* d_out, int out_size)
{
    const float* x   = (const float*)d_in[0];
    const float* W1  = (const float*)d_in[1];
    const float* b1  = (const float*)d_in[2];
    const float* g1  = (const float*)d_in[3];
    const float* be1 = (const float*)d_in[4];
    const float* W2  = (const float*)d_in[5];
    const float* b2  = (const float*)d_in[6];
    const float* g2  = (const float*)d_in[7];
    const float* be2 = (const float*)d_in[8];
    float* out = (float*)d_out;

    (void)in_sizes; (void)n_in; (void)out_size;

    const size_t g1_smem = G1_SMEM_FLOATS * sizeof(float);   // 166912 B
    const size_t g2_smem = G2_SMEM_FLOATS * sizeof(float);   // 201728 B
    cudaFuncSetAttribute(gemm1_ln_kernel,
                         cudaFuncAttributeMaxDynamicSharedMemorySize, (int)g1_smem);
    cudaFuncSetAttribute(gemm2_ln_kernel,
                         cudaFuncAttributeMaxDynamicSharedMemorySize, (int)g2_smem);

    gemm1_ln_kernel<<<NROWS/64, 256, g1_smem>>>(x, W1, b1, g1, be1);
    lif1_kernel<<<(BB*HH)/256, 256>>>();
    gemm2_ln_kernel<<<NROWS/64, 256, g2_smem>>>(W2, b2, g2, be2);
    lif2_kernel<<<(BB*DD)/256, 256>>>(x, out);
}